// round 4
// baseline (speedup 1.0000x reference)
#include <cuda_runtime.h>
#include <stdint.h>

// Problem constants
#define BB 16
#define DD 256
#define TT 2048
#define KK 8192
#define NN (BB*TT)            // 32768 tokens
#define OUTQ (BB*DD*TT)       // 8388608 floats of quantized_st
// Output layout: [quantized_st (OUTQ)][loss (1)][idx (NN)]

#define TM   32               // tokens per block
#define TKC  512              // codes per kc chunk
#define DK   16               // d-slice

#define ZROW 272              // bytes per d-row of zs2 (32 dup-pairs + swizzle pad)
#define ZS_BYTES (256*ZROW)   // 69632
#define EROW 2048             // bytes per d-row of es (512 floats)
#define EBUF_BYTES (DK*EROW)  // 32768
#define ES_BYTES (2*EBUF_BYTES)
#define SB_BYTES (8*32*8)     // 2048
#define SMEM_TOTAL (ZS_BYTES + ES_BYTES + SB_BYTES)

__device__ float g_enorm[KK];
__device__ float g_rnorm[NN];
__device__ int   g_idx[NN];
__device__ float g_loss;

// token-group swizzled column (bytes) inside a zs2 d-row: conflict-free LDS.128
__device__ __forceinline__ int zcol(int t) {
    return (t >> 3) * 64 + ((t >> 3) & 2) * 8 + (t & 7) * 8;
}
// chunk-interleaved column (bytes) inside an es d-row: code c -> [j][group][16B]
__device__ __forceinline__ int ecol(int c) {
    return ((c & 7) >> 2) * 1024 + ((c >> 3) << 4) + (c & 3) * 4;
}

// ---------------------------------------------------------------------------
__global__ void k_enorm(const float* __restrict__ emb) {
    int gw = (blockIdx.x * blockDim.x + threadIdx.x) >> 5;
    int lane = threadIdx.x & 31;
    if (gw >= KK) return;
    const float* row = emb + (size_t)gw * DD;
    float s = 0.f;
    #pragma unroll
    for (int i = 0; i < 8; i++) {
        float v = row[lane + 32 * i];
        s = __fadd_rn(s, __fmul_rn(v, v));
    }
    #pragma unroll
    for (int o = 16; o; o >>= 1) s = __fadd_rn(s, __shfl_down_sync(0xffffffffu, s, o));
    if (lane == 0) g_enorm[gw] = s;
}

__global__ void k_rnorm(const float* __restrict__ z) {
    int n = (blockIdx.x * blockDim.x + threadIdx.x) >> 5;
    int lane = threadIdx.x & 31;
    if (n >= NN) return;
    int b = n >> 11, t = n & (TT - 1);
    const float* zp = z + (size_t)b * DD * TT + t;
    float s = 0.f;
    #pragma unroll
    for (int i = 0; i < 8; i++) {
        float v = zp[(size_t)(lane + 32 * i) * TT];
        s = __fadd_rn(s, __fmul_rn(v, v));
    }
    #pragma unroll
    for (int o = 16; o; o >>= 1) s = __fadd_rn(s, __shfl_down_sync(0xffffffffu, s, o));
    if (lane == 0) g_rnorm[n] = s;
}

__global__ void k_zero() { g_loss = 0.f; }

// ---------------------------------------------------------------------------
// Argmin GEMM round 3: thread tile 8 tokens x 8 codes, conflict-free LDS,
// 32 FFMA2 per 6 LDS.128 per dd. Rounding chain identical to reference.
// ---------------------------------------------------------------------------
__global__ __launch_bounds__(256, 1) void k_argmin(
    const float* __restrict__ z, const float* __restrict__ emb,
    float* __restrict__ out, int write_idx)
{
    extern __shared__ char smem[];
    char* zs = smem;                       // [256][ZROW] dup z, swizzled
    char* es = smem + ZS_BYTES;            // [2][DK][EROW] chunk-interleaved e
    unsigned long long* sbest = (unsigned long long*)(smem + ZS_BYTES + ES_BYTES);

    const int tid  = threadIdx.x;
    const int lane = tid & 31;
    const int wq   = tid >> 5;            // warp -> 64-code strip
    const int lx   = lane & 7;            // code group within warp
    const int ly   = lane >> 3;           // token group (8 tokens)
    const int m0   = blockIdx.x * TM;
    const int b    = m0 >> 11, t0 = m0 & (TT - 1);
    const float* zb = z + (size_t)b * DD * TT + t0;

    const int g     = wq * 8 + lx;        // thread code-group 0..63
    const int cx    = g * 8;              // first code (block-local)
    const int zbase = ly * 64 + (ly & 2) * 8;   // swizzled token-group base (bytes)

    // ---- stage duplicated z once: 32 elems/thread, coalesced over t ----
    #pragma unroll 4
    for (int it = 0; it < 32; it++) {
        int u = tid + it * 256;
        int d = u >> 5, t = u & 31;
        float v = zb[(size_t)d * TT + t];
        *(float2*)(zs + d * ZROW + zcol(t)) = make_float2(v, v);
    }

    float rrow[8];
    #pragma unroll
    for (int t = 0; t < 8; t++) rrow[t] = g_rnorm[m0 + ly * 8 + t];

    unsigned long long best[8];
    #pragma unroll
    for (int t = 0; t < 8; t++) best[t] = ~0ull;

    unsigned long long acc[8][4];
    float4 pf[8];

    // ---- prologue: stage slice 0 into buffer 0 ----
    #pragma unroll
    for (int it = 0; it < 8; it++) {
        int u = tid + it * 256;
        int k = u & 511, dq = u >> 9;
        pf[it] = *(const float4*)(emb + (size_t)k * DD + dq * 4);
    }
    #pragma unroll
    for (int it = 0; it < 8; it++) {
        int u = tid + it * 256;
        int k = u & 511, dq = u >> 9;
        float* p = (float*)(es + (dq * 4) * EROW + ecol(k));
        p[0 * 512] = pf[it].x; p[1 * 512] = pf[it].y;
        p[2 * 512] = pf[it].z; p[3 * 512] = pf[it].w;
    }
    __syncthreads();

    #pragma unroll 1
    for (int s = 0; s < 256; s++) {
        const int kc = s >> 4;
        const int ds = (s & 15) * DK;

        if ((s & 15) == 0) {
            #pragma unroll
            for (int t = 0; t < 8; t++)
                #pragma unroll
                for (int j = 0; j < 4; j++) acc[t][j] = 0ull;
        }

        // prefetch next slice into registers
        const int sn = s + 1;
        if (sn < 256) {
            const int kcn = sn >> 4, dsn = (sn & 15) * DK;
            #pragma unroll
            for (int it = 0; it < 8; it++) {
                int u = tid + it * 256;
                int k = u & 511, dq = u >> 9;
                pf[it] = *(const float4*)(emb + (size_t)(kcn * TKC + k) * DD + dsn + dq * 4);
            }
        }

        // ---- compute current slice (conflict-free broadcast LDS) ----
        const char* eb = es + (s & 1) * EBUF_BYTES;
        #pragma unroll
        for (int dd = 0; dd < DK; dd++) {
            const char* ep = eb + dd * EROW + g * 16;
            ulonglong2 E0 = *(const ulonglong2*)(ep);          // codes cx+0..3
            ulonglong2 E1 = *(const ulonglong2*)(ep + 1024);   // codes cx+4..7
            const char* zp = zs + (ds + dd) * ZROW + zbase;
            ulonglong2 Z0 = *(const ulonglong2*)(zp);
            ulonglong2 Z1 = *(const ulonglong2*)(zp + 16);
            ulonglong2 Z2 = *(const ulonglong2*)(zp + 32);
            ulonglong2 Z3 = *(const ulonglong2*)(zp + 48);
            unsigned long long zz[8] = { Z0.x, Z0.y, Z1.x, Z1.y, Z2.x, Z2.y, Z3.x, Z3.y };
            #pragma unroll
            for (int t = 0; t < 8; t++) {
                asm("fma.rn.f32x2 %0, %1, %2, %0;" : "+l"(acc[t][0]) : "l"(zz[t]), "l"(E0.x));
                asm("fma.rn.f32x2 %0, %1, %2, %0;" : "+l"(acc[t][1]) : "l"(zz[t]), "l"(E0.y));
                asm("fma.rn.f32x2 %0, %1, %2, %0;" : "+l"(acc[t][2]) : "l"(zz[t]), "l"(E1.x));
                asm("fma.rn.f32x2 %0, %1, %2, %0;" : "+l"(acc[t][3]) : "l"(zz[t]), "l"(E1.y));
            }
        }

        // store prefetched slice into the other buffer
        if (sn < 256) {
            char* ebn = es + (sn & 1) * EBUF_BYTES;
            #pragma unroll
            for (int it = 0; it < 8; it++) {
                int u = tid + it * 256;
                int k = u & 511, dq = u >> 9;
                float* p = (float*)(ebn + (dq * 4) * EROW + ecol(k));
                p[0 * 512] = pf[it].x; p[1 * 512] = pf[it].y;
                p[2 * 512] = pf[it].z; p[3 * 512] = pf[it].w;
            }
        }
        __syncthreads();

        // ---- epilogue per kc chunk ----
        if ((s & 15) == 15) {
            #pragma unroll
            for (int jp = 0; jp < 4; jp++) {
                int c0 = kc * TKC + cx + jp * 2;
                float en0 = g_enorm[c0], en1 = g_enorm[c0 + 1];
                #pragma unroll
                for (int t = 0; t < 8; t++) {
                    float slo = __uint_as_float((unsigned)(acc[t][jp] & 0xffffffffull));
                    float shi = __uint_as_float((unsigned)(acc[t][jp] >> 32));
                    float d0 = __fsub_rn(__fadd_rn(rrow[t], en0), __fmul_rn(2.0f, slo));
                    float d1 = __fsub_rn(__fadd_rn(rrow[t], en1), __fmul_rn(2.0f, shi));
                    unsigned long long p0 =
                        ((unsigned long long)__float_as_uint(d0) << 32) | (unsigned)c0;
                    unsigned long long p1 =
                        ((unsigned long long)__float_as_uint(d1) << 32) | (unsigned)(c0 + 1);
                    if (p0 < best[t]) best[t] = p0;
                    if (p1 < best[t]) best[t] = p1;
                }
            }
        }
    }

    // ---- reduce across lx lanes (same tokens, different codes) ----
    #pragma unroll
    for (int t = 0; t < 8; t++) {
        unsigned long long p = best[t];
        unsigned long long q;
        q = __shfl_xor_sync(0xffffffffu, p, 1); if (q < p) p = q;
        q = __shfl_xor_sync(0xffffffffu, p, 2); if (q < p) p = q;
        q = __shfl_xor_sync(0xffffffffu, p, 4); if (q < p) p = q;
        if (lx == 0) sbest[wq * 32 + ly * 8 + t] = p;
    }
    __syncthreads();

    // ---- reduce across warps; write idx ----
    if (tid < 32) {
        unsigned long long p = sbest[tid];
        #pragma unroll
        for (int w = 1; w < 8; w++) {
            unsigned long long q = sbest[w * 32 + tid];
            if (q < p) p = q;
        }
        int kb = (int)(p & 0xffffffffull);
        int n = m0 + tid;
        g_idx[n] = kb;
        if (write_idx) out[(size_t)OUTQ + 1 + n] = (float)kb;
    }
}

// ---------------------------------------------------------------------------
__global__ void k_gather(const float* __restrict__ z, const float* __restrict__ emb,
                         float* __restrict__ out) {
    __shared__ int sk[32];
    __shared__ float red[8];
    int m0 = blockIdx.x * 32;
    int b = m0 >> 11, t0 = m0 & (TT - 1);
    int tid = threadIdx.x;
    if (tid < 32) sk[tid] = g_idx[m0 + tid];
    __syncthreads();
    int tt = tid & 31, dg = tid >> 5;
    size_t base = (size_t)b * DD * TT + t0 + tt;
    const float* erow = emb + (size_t)sk[tt] * DD;
    float s = 0.f;
    #pragma unroll
    for (int l = 0; l < 32; l++) {
        int d = dg * 32 + l;
        float q  = erow[d];
        float zv = z[base + (size_t)d * TT];
        float df = __fsub_rn(q, zv);
        out[base + (size_t)d * TT] = __fadd_rn(zv, df);
        s = __fmaf_rn(df, df, s);
    }
    #pragma unroll
    for (int o = 16; o; o >>= 1) s += __shfl_xor_sync(0xffffffffu, s, o);
    if ((tid & 31) == 0) red[tid >> 5] = s;
    __syncthreads();
    if (tid < 8) {
        s = red[tid];
        #pragma unroll
        for (int o = 4; o; o >>= 1) s += __shfl_xor_sync(0x000000ffu, s, o);
        if (tid == 0) atomicAdd(&g_loss, s);
    }
}

__global__ void k_final(float* __restrict__ out, int write_loss) {
    if (write_loss) {
        float m = g_loss / (float)OUTQ;
        out[OUTQ] = __fmul_rn(1.25f, m);
    }
}

// ---------------------------------------------------------------------------
extern "C" void kernel_launch(void* const* d_in, const int* in_sizes, int n_in,
                              void* d_out, int out_size) {
    const float* z   = (const float*)d_in[0];   // [B, D, T]
    const float* emb = (const float*)d_in[1];   // [K, D]
    float* out = (float*)d_out;

    int write_idx  = (out_size >= OUTQ + 1 + NN) ? 1 : 0;
    int write_loss = (out_size >= OUTQ + 1) ? 1 : 0;

    cudaFuncSetAttribute(k_argmin, cudaFuncAttributeMaxDynamicSharedMemorySize, SMEM_TOTAL);

    k_enorm <<<KK / 8, 256>>>(emb);
    k_rnorm <<<NN / 8, 256>>>(z);
    k_zero  <<<1, 1>>>();
    k_argmin<<<NN / TM, 256, SMEM_TOTAL>>>(z, emb, out, write_idx);
    k_gather<<<NN / 32, 256>>>(z, emb, out);
    k_final <<<1, 1>>>(out, write_loss);
}

// round 6
// speedup vs baseline: 1.1365x; 1.1365x over previous
#include <cuda_runtime.h>
#include <stdint.h>

// Problem constants
#define BB 16
#define DD 256
#define TT 2048
#define KK 8192
#define NN (BB*TT)            // 32768 tokens
#define OUTQ (BB*DD*TT)       // 8388608 floats of quantized_st
// Output layout: [quantized_st (OUTQ)][loss (1)][idx (NN)]

// argmin GEMM tiling
#define TM    32              // tokens per block
#define KCHNK 1024            // codes per chunk (per block, 8 warps x 128)
#define DK    8               // d per slice
#define NSLC  256             // total slices: (DD/DK) * (KK/KCHNK) = 32*8
#define ESLICE_F 8192         // floats per es slice buffer (DK*KCHNK)
#define ZS_F   (DD*TM)        // 8192 floats
#define SB_BYTES (8*32*8)     // 2048 bytes: 8 warps x 32 tokens x u64  (round-5 bug: was 256)
#define SMEM_TOTAL (ZS_F*4 + 3*ESLICE_F*4 + SB_BYTES + 64)

__device__ float g_embT[DD * KK];   // transposed embedding [D][K] (8 MB static)
__device__ float g_enorm[KK];
__device__ float g_rnorm[NN];
__device__ int   g_idx[NN];
__device__ float g_loss;

// ---------------------------------------------------------------------------
__global__ void k_enorm(const float* __restrict__ emb) {
    int gw = (blockIdx.x * blockDim.x + threadIdx.x) >> 5;
    int lane = threadIdx.x & 31;
    if (gw >= KK) return;
    const float* row = emb + (size_t)gw * DD;
    float s = 0.f;
    #pragma unroll
    for (int i = 0; i < 8; i++) {
        float v = row[lane + 32 * i];
        s = __fadd_rn(s, __fmul_rn(v, v));
    }
    #pragma unroll
    for (int o = 16; o; o >>= 1) s = __fadd_rn(s, __shfl_down_sync(0xffffffffu, s, o));
    if (lane == 0) g_enorm[gw] = s;
}

// rnorm: DO NOT change arithmetic order (part of reproduced rounding chain)
__global__ void k_rnorm(const float* __restrict__ z) {
    int n = (blockIdx.x * blockDim.x + threadIdx.x) >> 5;
    int lane = threadIdx.x & 31;
    if (n >= NN) return;
    int b = n >> 11, t = n & (TT - 1);
    const float* zp = z + (size_t)b * DD * TT + t;
    float s = 0.f;
    #pragma unroll
    for (int i = 0; i < 8; i++) {
        float v = zp[(size_t)(lane + 32 * i) * TT];
        s = __fadd_rn(s, __fmul_rn(v, v));
    }
    #pragma unroll
    for (int o = 16; o; o >>= 1) s = __fadd_rn(s, __shfl_down_sync(0xffffffffu, s, o));
    if (lane == 0) g_rnorm[n] = s;
}

__global__ void k_zero() { g_loss = 0.f; }

// ---------------------------------------------------------------------------
// emb [K][D] -> g_embT [D][K], 32x32 smem tiles
// ---------------------------------------------------------------------------
__global__ void k_transpose(const float* __restrict__ emb) {
    __shared__ float tile[32][33];
    int kb = blockIdx.x * 32, db = blockIdx.y * 32;
    int x = threadIdx.x, y = threadIdx.y;   // block (32, 8)
    #pragma unroll
    for (int i = 0; i < 32; i += 8)
        tile[y + i][x] = emb[(size_t)(kb + y + i) * DD + db + x];
    __syncthreads();
    #pragma unroll
    for (int i = 0; i < 32; i += 8)
        g_embT[(size_t)(db + y + i) * KK + kb + x] = tile[x][y + i];
}

// ---------------------------------------------------------------------------
// Argmin GEMM:
//  - thread tile 8 tokens x 16 codes (64 f32x2 accumulators)
//  - z natural in smem, (z,z) duplication via mov.b64 in registers
//  - e staged from pre-transposed g_embT via cp.async (3-stage ring),
//    chunk-interleaved layout -> phase-contiguous LDS.128, zero conflicts
//  - rounding chain identical to reference:
//      dist = fl( fl(rnorm + enorm) - fl(2*dot) ), dot accumulated d-ascending
// ---------------------------------------------------------------------------
__global__ __launch_bounds__(256, 1) void k_argmin(
    const float* __restrict__ z,
    float* __restrict__ out, int write_idx)
{
    extern __shared__ char smem[];
    float* zs = (float*)smem;                          // [256][32] natural z
    float* es = (float*)(smem + ZS_F * 4);             // [3][DK][KCHNK] interleaved
    unsigned long long* sbest = (unsigned long long*)(smem + ZS_F * 4 + 3 * ESLICE_F * 4);

    const int tid  = threadIdx.x;
    const int lane = tid & 31;
    const int wq   = tid >> 5;          // warp -> 128-code strip within chunk
    const int lx   = lane & 7;          // code group within warp (16 codes)
    const int ly   = lane >> 3;         // token group (8 tokens)
    const int g    = wq * 8 + lx;       // thread code-slot 0..63
    const int m0   = blockIdx.x * TM;
    const int b    = m0 >> 11, t0 = m0 & (TT - 1);

    const unsigned es_u32 = (unsigned)__cvta_generic_to_shared(es);

    // ---- stage z once: [d][t] natural, 8 float4 per thread, coalesced ----
    {
        const float* zb = z + (size_t)b * DD * TT + t0;
        #pragma unroll
        for (int it = 0; it < 8; it++) {
            int u = tid + it * 256;
            int d = u >> 3, tq = u & 7;
            float4 v = *(const float4*)(zb + (size_t)d * TT + tq * 4);
            *(float4*)(zs + d * 32 + tq * 4) = v;
        }
    }

    float rrow[8];
    #pragma unroll
    for (int t = 0; t < 8; t++) rrow[t] = g_rnorm[m0 + ly * 8 + t];

    unsigned long long best[8];
    #pragma unroll
    for (int t = 0; t < 8; t++) best[t] = ~0ull;

    unsigned long long acc[8][8];

    // slice sl: chunk kcb = sl>>5, d-base dsb = (sl&31)*8
    // es layout per slice: [dd][j 0..3][slot 0..63][16B]
    #define STAGE(sl)                                                           \
    do {                                                                        \
        int _kcb = (sl) >> 5, _dsb = ((sl) & 31) * 8;                           \
        unsigned _dstb = es_u32 + ((sl) % 3) * (ESLICE_F * 4);                  \
        _Pragma("unroll")                                                       \
        for (int _it = 0; _it < 8; _it++) {                                     \
            int _u = tid + _it * 256;                                           \
            int _dd = _u >> 8, _c4 = _u & 255;                                  \
            const float* _src = g_embT + (size_t)(_dsb + _dd) * KK              \
                                + _kcb * KCHNK + _c4 * 4;                       \
            unsigned _dst = _dstb + _dd * 4096 + (_c4 & 3) * 1024               \
                            + (_c4 >> 2) * 16;                                  \
            asm volatile("cp.async.cg.shared.global [%0], [%1], 16;"            \
                         :: "r"(_dst), "l"(_src));                              \
        }                                                                       \
        asm volatile("cp.async.commit_group;");                                 \
    } while (0)

    // prologue: two slices in flight
    STAGE(0);
    STAGE(1);
    __syncthreads();   // zs visible to all before first compute

    #pragma unroll 1
    for (int s = 0; s < NSLC; s++) {
        asm volatile("cp.async.wait_group 1;");   // slice s complete (s+1 pending)
        __syncthreads();                          // all data visible; all done with s-1

        if (s + 2 < NSLC) STAGE(s + 2);           // overwrites s-1's buffer (safe)

        if ((s & 31) == 0) {
            #pragma unroll
            for (int t = 0; t < 8; t++)
                #pragma unroll
                for (int j = 0; j < 8; j++) acc[t][j] = 0ull;
        }

        const float* eb = es + (s % 3) * ESLICE_F;
        const int ds = (s & 31) * DK;

        #pragma unroll
        for (int dd = 0; dd < DK; dd++) {
            const float* ep = eb + dd * 1024 + g * 4;
            ulonglong2 E0 = *(const ulonglong2*)(ep);         // codes base+0..3
            ulonglong2 E1 = *(const ulonglong2*)(ep + 256);   // codes base+4..7
            ulonglong2 E2 = *(const ulonglong2*)(ep + 512);   // codes base+8..11
            ulonglong2 E3 = *(const ulonglong2*)(ep + 768);   // codes base+12..15
            const float* zp = zs + (ds + dd) * 32 + ly * 8;
            float4 za = *(const float4*)(zp);
            float4 zb4 = *(const float4*)(zp + 4);
            unsigned long long zz[8];
            asm("mov.b64 %0, {%1,%1};" : "=l"(zz[0]) : "r"(__float_as_uint(za.x)));
            asm("mov.b64 %0, {%1,%1};" : "=l"(zz[1]) : "r"(__float_as_uint(za.y)));
            asm("mov.b64 %0, {%1,%1};" : "=l"(zz[2]) : "r"(__float_as_uint(za.z)));
            asm("mov.b64 %0, {%1,%1};" : "=l"(zz[3]) : "r"(__float_as_uint(za.w)));
            asm("mov.b64 %0, {%1,%1};" : "=l"(zz[4]) : "r"(__float_as_uint(zb4.x)));
            asm("mov.b64 %0, {%1,%1};" : "=l"(zz[5]) : "r"(__float_as_uint(zb4.y)));
            asm("mov.b64 %0, {%1,%1};" : "=l"(zz[6]) : "r"(__float_as_uint(zb4.z)));
            asm("mov.b64 %0, {%1,%1};" : "=l"(zz[7]) : "r"(__float_as_uint(zb4.w)));
            #pragma unroll
            for (int t = 0; t < 8; t++) {
                asm("fma.rn.f32x2 %0, %1, %2, %0;" : "+l"(acc[t][0]) : "l"(zz[t]), "l"(E0.x));
                asm("fma.rn.f32x2 %0, %1, %2, %0;" : "+l"(acc[t][1]) : "l"(zz[t]), "l"(E0.y));
                asm("fma.rn.f32x2 %0, %1, %2, %0;" : "+l"(acc[t][2]) : "l"(zz[t]), "l"(E1.x));
                asm("fma.rn.f32x2 %0, %1, %2, %0;" : "+l"(acc[t][3]) : "l"(zz[t]), "l"(E1.y));
                asm("fma.rn.f32x2 %0, %1, %2, %0;" : "+l"(acc[t][4]) : "l"(zz[t]), "l"(E2.x));
                asm("fma.rn.f32x2 %0, %1, %2, %0;" : "+l"(acc[t][5]) : "l"(zz[t]), "l"(E2.y));
                asm("fma.rn.f32x2 %0, %1, %2, %0;" : "+l"(acc[t][6]) : "l"(zz[t]), "l"(E3.x));
                asm("fma.rn.f32x2 %0, %1, %2, %0;" : "+l"(acc[t][7]) : "l"(zz[t]), "l"(E3.y));
            }
        }

        // ---- epilogue per chunk ----
        if ((s & 31) == 31) {
            int cbase = (s >> 5) * KCHNK + g * 16;
            #pragma unroll
            for (int ch = 0; ch < 4; ch++) {
                #pragma unroll
                for (int p = 0; p < 2; p++) {
                    int c0 = cbase + ch * 4 + p * 2;
                    float en0 = g_enorm[c0], en1 = g_enorm[c0 + 1];
                    #pragma unroll
                    for (int t = 0; t < 8; t++) {
                        unsigned long long a = acc[t][ch * 2 + p];
                        float slo = __uint_as_float((unsigned)(a & 0xffffffffull));
                        float shi = __uint_as_float((unsigned)(a >> 32));
                        float d0 = __fsub_rn(__fadd_rn(rrow[t], en0), __fmul_rn(2.0f, slo));
                        float d1 = __fsub_rn(__fadd_rn(rrow[t], en1), __fmul_rn(2.0f, shi));
                        unsigned long long p0 =
                            ((unsigned long long)__float_as_uint(d0) << 32) | (unsigned)c0;
                        unsigned long long p1 =
                            ((unsigned long long)__float_as_uint(d1) << 32) | (unsigned)(c0 + 1);
                        if (p0 < best[t]) best[t] = p0;
                        if (p1 < best[t]) best[t] = p1;
                    }
                }
            }
        }
    }

    // ---- reduce over lx lanes (same tokens, different codes) ----
    #pragma unroll
    for (int t = 0; t < 8; t++) {
        unsigned long long p = best[t];
        unsigned long long q;
        q = __shfl_xor_sync(0xffffffffu, p, 1); if (q < p) p = q;
        q = __shfl_xor_sync(0xffffffffu, p, 2); if (q < p) p = q;
        q = __shfl_xor_sync(0xffffffffu, p, 4); if (q < p) p = q;
        if (lx == 0) sbest[wq * 32 + ly * 8 + t] = p;
    }
    __syncthreads();

    // ---- reduce across warps; write idx ----
    if (tid < 32) {
        unsigned long long p = sbest[tid];
        #pragma unroll
        for (int w = 1; w < 8; w++) {
            unsigned long long q = sbest[w * 32 + tid];
            if (q < p) p = q;
        }
        int kb = (int)(p & 0xffffffffull);
        int n = m0 + tid;
        g_idx[n] = kb;
        if (write_idx) out[(size_t)OUTQ + 1 + n] = (float)kb;
    }
    #undef STAGE
}

// ---------------------------------------------------------------------------
__global__ void k_gather(const float* __restrict__ z, const float* __restrict__ emb,
                         float* __restrict__ out) {
    __shared__ int sk[32];
    __shared__ float red[8];
    int m0 = blockIdx.x * 32;
    int b = m0 >> 11, t0 = m0 & (TT - 1);
    int tid = threadIdx.x;
    if (tid < 32) sk[tid] = g_idx[m0 + tid];
    __syncthreads();
    int tt = tid & 31, dg = tid >> 5;
    size_t base = (size_t)b * DD * TT + t0 + tt;
    const float* erow = emb + (size_t)sk[tt] * DD;
    float s = 0.f;
    #pragma unroll
    for (int l = 0; l < 32; l++) {
        int d = dg * 32 + l;
        float q  = erow[d];
        float zv = z[base + (size_t)d * TT];
        float df = __fsub_rn(q, zv);
        out[base + (size_t)d * TT] = __fadd_rn(zv, df);
        s = __fmaf_rn(df, df, s);
    }
    #pragma unroll
    for (int o = 16; o; o >>= 1) s += __shfl_xor_sync(0xffffffffu, s, o);
    if ((tid & 31) == 0) red[tid >> 5] = s;
    __syncthreads();
    if (tid < 8) {
        s = red[tid];
        #pragma unroll
        for (int o = 4; o; o >>= 1) s += __shfl_xor_sync(0x000000ffu, s, o);
        if (tid == 0) atomicAdd(&g_loss, s);
    }
}

__global__ void k_final(float* __restrict__ out, int write_loss) {
    if (write_loss) {
        float m = g_loss / (float)OUTQ;
        out[OUTQ] = __fmul_rn(1.25f, m);
    }
}

// ---------------------------------------------------------------------------
extern "C" void kernel_launch(void* const* d_in, const int* in_sizes, int n_in,
                              void* d_out, int out_size) {
    const float* z   = (const float*)d_in[0];   // [B, D, T]
    const float* emb = (const float*)d_in[1];   // [K, D]
    float* out = (float*)d_out;

    int write_idx  = (out_size >= OUTQ + 1 + NN) ? 1 : 0;
    int write_loss = (out_size >= OUTQ + 1) ? 1 : 0;

    cudaFuncSetAttribute(k_argmin, cudaFuncAttributeMaxDynamicSharedMemorySize, SMEM_TOTAL);

    k_transpose<<<dim3(KK / 32, DD / 32), dim3(32, 8)>>>(emb);
    k_enorm <<<KK / 8, 256>>>(emb);
    k_rnorm <<<NN / 8, 256>>>(z);
    k_zero  <<<1, 1>>>();
    k_argmin<<<NN / TM, 256, SMEM_TOTAL>>>(z, out, write_idx);
    k_gather<<<NN / 32, 256>>>(z, emb, out);
    k_final <<<1, 1>>>(out, write_loss);
}

// round 7
// speedup vs baseline: 1.2750x; 1.1219x over previous
#include <cuda_runtime.h>
#include <stdint.h>

// Problem constants
#define BB 16
#define DD 256
#define TT 2048
#define KK 8192
#define NN (BB*TT)            // 32768 tokens
#define OUTQ (BB*DD*TT)       // 8388608 floats of quantized_st
// Output layout: [quantized_st (OUTQ)][loss (1)][idx (NN)]

__device__ float g_enorm[KK];
__device__ float g_rnorm[NN];
__device__ float g_loss;

// ---------------------------------------------------------------------------
// enorm[k] = sum_d emb[k][d]^2  (one warp per code; order sub-ulp irrelevant)
// ---------------------------------------------------------------------------
__global__ void k_enorm(const float* __restrict__ emb) {
    int gw = (blockIdx.x * blockDim.x + threadIdx.x) >> 5;
    int lane = threadIdx.x & 31;
    if (gw >= KK) return;
    const float* row = emb + (size_t)gw * DD;
    float s = 0.f;
    #pragma unroll
    for (int i = 0; i < 8; i++) {
        float v = row[lane + 32 * i];
        s = __fadd_rn(s, __fmul_rn(v, v));
    }
    #pragma unroll
    for (int o = 16; o; o >>= 1) s = __fadd_rn(s, __shfl_down_sync(0xffffffffu, s, o));
    if (lane == 0) g_enorm[gw] = s;
}

// ---------------------------------------------------------------------------
// rnorm[n] = sum_d z[b][d][t]^2 — exact order is load-bearing (rounding chain)
// ---------------------------------------------------------------------------
__global__ void k_rnorm(const float* __restrict__ z) {
    int n = (blockIdx.x * blockDim.x + threadIdx.x) >> 5;
    int lane = threadIdx.x & 31;
    if (n >= NN) return;
    int b = n >> 11, t = n & (TT - 1);
    const float* zp = z + (size_t)b * DD * TT + t;
    float s = 0.f;
    #pragma unroll
    for (int i = 0; i < 8; i++) {
        float v = zp[(size_t)(lane + 32 * i) * TT];
        s = __fadd_rn(s, __fmul_rn(v, v));
    }
    #pragma unroll
    for (int o = 16; o; o >>= 1) s = __fadd_rn(s, __shfl_down_sync(0xffffffffu, s, o));
    if (lane == 0) g_rnorm[n] = s;
}

__global__ void k_zero() { g_loss = 0.f; }

// ---------------------------------------------------------------------------
// Argmin "GEMM" — round-1 configuration (measured 99% of fp32 FMA floor):
// block tile 64 tokens x 256 codes, Dk=32 slices over D=256, 256 threads,
// thread = 8 tokens x 8 codes as 8x4 f32x2 accumulators (codes k, k+32 pairs).
// Distance reproduces the reference rounding chain exactly:
//   dist = fl( fl(rnorm + enorm) - fl(2 * dot) ), dot accumulated d-ascending,
//   argmin first-index ties.
// NEW: gather + loss partials fused into the block tail (saves k_gather).
// ---------------------------------------------------------------------------
#define TM  64
#define TKC 256
#define DK  32

__global__ __launch_bounds__(256, 1) void k_argmin(
    const float* __restrict__ z, const float* __restrict__ emb,
    float* __restrict__ out, int write_idx)
{
    __shared__ float zs[DK][TM];
    __shared__ float es[DK][TKC + 1];
    __shared__ int   skidx[TM];
    __shared__ float lred[8];

    const int tid = threadIdx.x;
    const int tx = tid & 31;       // code group (lane)
    const int ty = tid >> 5;       // token group (warp)
    const int m0 = blockIdx.x * TM;
    const int b = m0 >> 11, t0 = m0 & (TT - 1);
    const float* zb = z + (size_t)b * DD * TT + t0;

    float bestd[8];
    int   besti[8];
    #pragma unroll
    for (int i = 0; i < 8; i++) { bestd[i] = __int_as_float(0x7f7fffff); besti[i] = 0; }

    float rrow[8];
    #pragma unroll
    for (int i = 0; i < 8; i++) rrow[i] = g_rnorm[m0 + ty + 8 * i];

    for (int kc = 0; kc < KK; kc += TKC) {
        unsigned long long acc[8][4];
        #pragma unroll
        for (int i = 0; i < 8; i++)
            #pragma unroll
            for (int j = 0; j < 4; j++) acc[i][j] = 0ull;   // packed (0.f, 0.f)

        for (int ds = 0; ds < DD; ds += DK) {
            __syncthreads();   // protect previous slice's reads
            // stage z tile [DK][TM]: contiguous 64-float rows, coalesced
            #pragma unroll
            for (int r = 0; r < (DK * TM) / 256; r++) {
                int idx = tid + r * 256;
                zs[idx >> 6][idx & 63] = zb[(size_t)(ds + (idx >> 6)) * TT + (idx & 63)];
            }
            // stage emb tile [DK][TKC]: 32-float segments per code, coalesced,
            // stride-257 rows -> conflict-free stores
            #pragma unroll
            for (int r = 0; r < (DK * TKC) / 256; r++) {
                int idx = tid + r * 256;
                int kk = idx >> 5, dd2 = idx & 31;
                es[dd2][kk] = emb[(size_t)(kc + kk) * DD + ds + dd2];
            }
            __syncthreads();

            #pragma unroll
            for (int dd = 0; dd < DK; dd++) {
                unsigned long long ev[4];
                #pragma unroll
                for (int j = 0; j < 4; j++) {
                    unsigned lo = __float_as_uint(es[dd][tx + 64 * j]);
                    unsigned hi = __float_as_uint(es[dd][tx + 32 + 64 * j]);
                    asm("mov.b64 %0, {%1,%2};" : "=l"(ev[j]) : "r"(lo), "r"(hi));
                }
                #pragma unroll
                for (int i = 0; i < 8; i++) {
                    unsigned zu = __float_as_uint(zs[dd][ty + 8 * i]);  // warp-broadcast
                    unsigned long long zz;
                    asm("mov.b64 %0, {%1,%1};" : "=l"(zz) : "r"(zu));
                    #pragma unroll
                    for (int j = 0; j < 4; j++)
                        asm("fma.rn.f32x2 %0, %1, %2, %0;"
                            : "+l"(acc[i][j]) : "l"(zz), "l"(ev[j]));
                }
            }
        }

        // epilogue: distances + running argmin (k ascending per thread ->
        // strict < keeps the earliest index automatically)
        #pragma unroll
        for (int j = 0; j < 4; j++) {
            int k0 = kc + tx + 64 * j;
            int k1 = k0 + 32;
            float e0 = g_enorm[k0], e1 = g_enorm[k1];
            #pragma unroll
            for (int i = 0; i < 8; i++) {
                unsigned lo, hi;
                asm("mov.b64 {%0,%1}, %2;" : "=r"(lo), "=r"(hi) : "l"(acc[i][j]));
                float d0 = __fsub_rn(__fadd_rn(rrow[i], e0),
                                     __fmul_rn(2.0f, __uint_as_float(lo)));
                float d1 = __fsub_rn(__fadd_rn(rrow[i], e1),
                                     __fmul_rn(2.0f, __uint_as_float(hi)));
                if (d0 < bestd[i]) { bestd[i] = d0; besti[i] = k0; }
                if (d1 < bestd[i]) { bestd[i] = d1; besti[i] = k1; }
            }
        }
    }

    // cross-lane reduction (all 32 code-groups of a token live in one warp);
    // ties -> smaller index, matching jnp.argmin
    #pragma unroll
    for (int i = 0; i < 8; i++) {
        float d = bestd[i]; int kb = besti[i];
        #pragma unroll
        for (int o = 16; o; o >>= 1) {
            float od = __shfl_xor_sync(0xffffffffu, d, o);
            int   ok = __shfl_xor_sync(0xffffffffu, kb, o);
            if (od < d || (od == d && ok < kb)) { d = od; kb = ok; }
        }
        if (tx == 0) {
            int tt = ty + 8 * i;
            skidx[tt] = kb;
            if (write_idx) out[(size_t)OUTQ + 1 + m0 + tt] = (float)kb;
        }
    }
    __syncthreads();

    // ---- fused gather + loss partials for this block's 64 tokens ----
    // thread: token tt = tid & 63, d-group dg = tid >> 6 (4 groups of 64 d).
    // out = fl(z + fl(q - z)) reproduces straight-through rounding exactly.
    {
        int tt = tid & 63, dg = tid >> 6;
        size_t base = (size_t)b * DD * TT + t0 + tt;
        const float* erow = emb + (size_t)skidx[tt] * DD;
        float s = 0.f;
        #pragma unroll 8
        for (int l = 0; l < 64; l++) {
            int d = dg * 64 + l;
            float q  = erow[d];
            float zv = z[base + (size_t)d * TT];
            float df = __fsub_rn(q, zv);
            out[base + (size_t)d * TT] = __fadd_rn(zv, df);
            s = __fmaf_rn(df, df, s);
        }
        #pragma unroll
        for (int o = 16; o; o >>= 1) s += __shfl_xor_sync(0xffffffffu, s, o);
        if ((tid & 31) == 0) lred[tid >> 5] = s;
        __syncthreads();
        if (tid < 8) {
            s = lred[tid];
            #pragma unroll
            for (int o = 4; o; o >>= 1) s += __shfl_xor_sync(0x000000ffu, s, o);
            if (tid == 0) atomicAdd(&g_loss, s);
        }
    }
}

__global__ void k_final(float* __restrict__ out, int write_loss) {
    if (write_loss) {
        float m = g_loss / (float)OUTQ;           // mean((q - z)^2)
        out[OUTQ] = __fmul_rn(1.25f, m);          // q_loss + 0.25 * e_loss
    }
}

// ---------------------------------------------------------------------------
extern "C" void kernel_launch(void* const* d_in, const int* in_sizes, int n_in,
                              void* d_out, int out_size) {
    const float* z   = (const float*)d_in[0];   // [B, D, T]
    const float* emb = (const float*)d_in[1];   // [K, D]
    float* out = (float*)d_out;

    int write_idx  = (out_size >= OUTQ + 1 + NN) ? 1 : 0;
    int write_loss = (out_size >= OUTQ + 1) ? 1 : 0;

    k_enorm <<<KK / 8, 256>>>(emb);
    k_rnorm <<<NN / 8, 256>>>(z);
    k_zero  <<<1, 1>>>();
    k_argmin<<<NN / TM, 256>>>(z, emb, out, write_idx);   // 4th launch -> profiled
    k_final <<<1, 1>>>(out, write_loss);
}